// round 15
// baseline (speedup 1.0000x reference)
#include <cuda_runtime.h>
#include <cuda_bf16.h>
#include <cstdint>
#include <cstddef>

// ---------------------------------------------------------------------------
// Problem: B=64, T=512, K=8, H=256 (4H=1024), HID1=100, HID2=128, OUT=24
// Output: pred (8,64,24) float32
//
// G layout is INTERLEAVED: G[t][b][il] with il = hk*4 + gate for gate row
// r = gate*256 + hk. For recurrence row rl (gate = rl&3, u = rl>>2,
// hk = rank*32+u): il = rank*128 + rl -> coalesced per warp.
// ---------------------------------------------------------------------------

__device__ float g_G[512u * 64u * 1024u];   // interleaved gate pre-activations
__device__ float g_h0[512u * 64u * 256u];   // layer-0 h, time-major [t][b][k]
__device__ float g_h1[512u * 64u * 256u];   // layer-1 h, time-major [t][b][k]
__device__ float g_hsum[64 * 256];          // sum_t h1
__device__ float g_a[64 * 128];             // m@Wl1.T + b1  (100 used)
__device__ float g_ypart[8 * 64 * 128];     // partial sums of y over t-chunks
__device__ float g_y511[64 * 128];          // y at t=511 (100 used)
__device__ float g_s[64 * 128];             // s = h2[:, -1, :]

// ---------------------------------------------------------------------------
// PTX helpers
// ---------------------------------------------------------------------------
__device__ __forceinline__ void cluster_sync_asm() {
    asm volatile("barrier.cluster.arrive.aligned;" ::: "memory");
    asm volatile("barrier.cluster.wait.aligned;" ::: "memory");
}

__device__ __forceinline__ uint32_t mapa_rank(uint32_t laddr, uint32_t rk) {
    uint32_t ra;
    asm volatile("mapa.shared::cluster.u32 %0, %1, %2;" : "=r"(ra) : "r"(laddr), "r"(rk));
    return ra;
}

__device__ __forceinline__ void st_cluster_f32(uint32_t raddr, float v) {
    asm volatile("st.shared::cluster.f32 [%0], %1;" :: "r"(raddr), "f"(v) : "memory");
}

__device__ __forceinline__ void mbar_arrive_addr(uint32_t raddr) {
    asm volatile("mbarrier.arrive.release.cluster.shared::cluster.b64 _, [%0];"
                 :: "r"(raddr) : "memory");
}

__device__ __forceinline__ void mbar_wait_cluster(uint32_t addr, uint32_t parity) {
    asm volatile(
        "{\n\t"
        ".reg .pred P;\n\t"
        "WL%=:\n\t"
        "mbarrier.try_wait.parity.acquire.cluster.shared::cta.b64 P, [%0], %1, 0x989680;\n\t"
        "@P bra.uni WD%=;\n\t"
        "bra.uni WL%=;\n\t"
        "WD%=:\n\t"
        "}" :: "r"(addr), "r"(parity) : "memory");
}

// packed f32x2 fused multiply-add: d = a*b + d
__device__ __forceinline__ void ffma2(unsigned long long& d,
                                      unsigned long long a, unsigned long long b) {
    asm("fma.rn.f32x2 %0, %1, %2, %3;" : "=l"(d) : "l"(a), "l"(b), "l"(d));
}
__device__ __forceinline__ float f2sum(unsigned long long v) {
    float2 f = *reinterpret_cast<float2*>(&v);
    return f.x + f.y;
}
__device__ __forceinline__ unsigned long long packdup(float a) {
    unsigned long long d;
    unsigned int ai = __float_as_uint(a);
    asm("mov.b64 %0, {%1, %1};" : "=l"(d) : "r"(ai));
    return d;
}

__device__ __forceinline__ float sigf(float x) {
    return __fdividef(1.0f, 1.0f + __expf(-x));
}
__device__ __forceinline__ float tanh_fast(float x) {
    return 2.0f * sigf(2.0f * x) - 1.0f;
}

// ---------------------------------------------------------------------------
// Phase A: G0[t][b][il(r)] = (bih0+bhh0)[r] + sum_k x[b][t][k]*Wih0[r][k]
// ---------------------------------------------------------------------------
__global__ void __launch_bounds__(256) phaseA_kernel(
    const float* __restrict__ x, const float* __restrict__ Wih0,
    const float* __restrict__ bih0, const float* __restrict__ bhh0,
    float* __restrict__ G)
{
    __shared__ float xs[16][8];
    int tid = threadIdx.x;
    int p0 = blockIdx.x * 16;

    float w[4][8];
    float bsv[4];
#pragma unroll
    for (int g = 0; g < 4; g++) {
        int r = tid + g * 256;
        const float4* wp = (const float4*)(Wih0 + (size_t)r * 8);
        float4 w0 = wp[0], w1 = wp[1];
        w[g][0] = w0.x; w[g][1] = w0.y; w[g][2] = w0.z; w[g][3] = w0.w;
        w[g][4] = w1.x; w[g][5] = w1.y; w[g][6] = w1.z; w[g][7] = w1.w;
        bsv[g] = bih0[r] + bhh0[r];
    }
    if (tid < 128) {
        int q = tid >> 3, k = tid & 7;
        int p = p0 + q;
        int b = p & 63, t = p >> 6;
        xs[q][k] = x[((size_t)b * 512 + t) * 8 + k];
    }
    __syncthreads();

    for (int q = 0; q < 16; q++) {
        size_t gb = (size_t)(p0 + q) * 1024;
        float4 out;
        float vv[4];
#pragma unroll
        for (int g = 0; g < 4; g++) {
            float acc = bsv[g];
#pragma unroll
            for (int k = 0; k < 8; k++) acc = fmaf(w[g][k], xs[q][k], acc);
            vv[g] = acc;
        }
        out.x = vv[0]; out.y = vv[1]; out.z = vv[2]; out.w = vv[3];
        *(float4*)&G[gb + (size_t)tid * 4] = out;   // il = tid*4 + g
    }
}

// ---------------------------------------------------------------------------
// LSTM recurrence (R13 structure + tail shave). 16 clusters x 8 CTAs
// (grid 128), 512 threads. Broadcast GEMV, quarter mbarriers now expect=8
// (4 owner warps x 2 ranks), per-warp arrives after __syncwarp (named
// barrier bar.sync 1,128 removed), owner reuses its own quarter-0 partials
// from registers instead of reloading red[0].
// ---------------------------------------------------------------------------
__global__ void __cluster_dims__(8, 1, 1) __launch_bounds__(512, 1)
lstm_recur_kernel(const float* __restrict__ G, const float* __restrict__ Whh,
                  float* __restrict__ hout, float* __restrict__ hsum, int dosum)
{
    __shared__ float hbuf[2][4][256];          // 8 KB, double-buffered
    __shared__ float4 red[4][4][32];           // [q][rb][lane] -> 8 KB
    __shared__ __align__(8) unsigned long long mbar[4];

    int tid = threadIdx.x;
    int rank = blockIdx.x & 7;
    int cl = blockIdx.x >> 3;
    int w = tid >> 5;
    int lane = tid & 31;
    int rb = w & 3;             // row-block
    int q = w >> 2;             // k-quarter (64 cols)
    int rl = rb * 32 + lane;    // row 0..127:  gate = rl&3, u = rl>>2
    int gate = rl & 3;
    int u = rl >> 2;
    int grow = gate * 256 + rank * 32 + u;

    // weights: 64 floats (quarter q of row grow) = 32 packed f32x2
    unsigned long long wreg[32];
    {
        const ulonglong2* wp = (const ulonglong2*)(Whh + (size_t)grow * 256 + q * 64);
#pragma unroll
        for (int i = 0; i < 16; i++) { ulonglong2 v = wp[i]; wreg[2 * i] = v.x; wreg[2 * i + 1] = v.y; }
    }

    for (int i = tid; i < 2 * 4 * 256; i += 512) (&hbuf[0][0][0])[i] = 0.0f;

    uint32_t mbar_addr = (uint32_t)__cvta_generic_to_shared(&mbar[0]);
    if (tid < 4) {
        uint32_t a = mbar_addr + tid * 8;
        asm volatile("mbarrier.init.shared.b64 [%0], 8;" :: "r"(a) : "memory");
    }

    // owner mapping (warps 0-3 only): lane -> (u_o = 8w + lane>>2, b_o = lane&3)
    int b_o = lane & 3;
    int u_o = 8 * w + (lane >> 2);
    int k_h = rank * 32 + u_o;
    uint32_t pbase[8];
    {
        uint32_t lp = (uint32_t)__cvta_generic_to_shared(&hbuf[0][b_o][k_h]);
#pragma unroll
        for (int r = 0; r < 8; r++) pbase[r] = mapa_rank(lp, (uint32_t)r);
    }
    // producer arrive target: each owner warp's lanes 0-7 arrive on barrier
    // (rank>>1) of ranks 0-7 (4 warps x 2 producer ranks = 8 per barrier)
    uint32_t marr = 0;
    if (w < 4 && lane < 8)
        marr = mapa_rank(mbar_addr + (uint32_t)(rank >> 1) * 8, (uint32_t)lane);
    // consumer wait address: barrier q (local)
    uint32_t mwait = mbar_addr + (uint32_t)q * 8;
    const uint32_t bstride = 4u * 256u * 4u;   // hbuf[1]-hbuf[0] in bytes

    // interleaved G pointer: il = rank*128 + rl (see header comment)
    const float* gbase = G + (size_t)(cl * 4) * 1024 + rank * 128 + rl;
    float* houtp = hout + (size_t)(cl * 4 + b_o) * 256 + k_h;

    float c = 0.0f, hs = 0.0f;
    __syncthreads();
    cluster_sync_asm();   // mbarriers initialized cluster-wide before any arrive

    float gin[4] = {0, 0, 0, 0};
    if (w < 4) {
#pragma unroll
        for (int b = 0; b < 4; b++) gin[b] = __ldg(gbase + b * 1024);
    }

    for (int t = 0; t < 512; t++) {
        int cur = t & 1;
        int nxt = cur ^ 1;

        // prefetch BEFORE the wait: LDG latency hides under barrier wait
        float ngin[4] = {0, 0, 0, 0};
        if (w < 4) {
            int tn = (t < 511) ? t + 1 : t;
            const float* gp = gbase + (size_t)tn * 65536;
#pragma unroll
            for (int b = 0; b < 4; b++) ngin[b] = __ldg(gp + b * 1024);
        }

        if (t > 0) {
            if (lane == 0) mbar_wait_cluster(mwait, (t + 1) & 1);
            __syncwarp();
        }

        // broadcast GEMV over quarter q
        float vals[4];
#pragma unroll
        for (int b = 0; b < 4; b++) {
            const ulonglong2* hp = (const ulonglong2*)&hbuf[cur][b][q * 64];
            unsigned long long a0 = 0ull, a1 = 0ull;
#pragma unroll
            for (int i = 0; i < 16; i++) {
                ulonglong2 hv = hp[i];
                ffma2(a0, wreg[2 * i], hv.x);
                ffma2(a1, wreg[2 * i + 1], hv.y);
            }
            vals[b] = f2sum(a0) + f2sum(a1);
        }
        if (q != 0)   // owner warps (q==0) keep their partials in registers
            red[q][rb][lane] = make_float4(vals[0], vals[1], vals[2], vals[3]);
        __syncthreads();   // stage-1 partials visible; hbuf[cur] reads done

        if (w < 4) {
            float4 s1 = red[1][w][lane];
            float4 s2 = red[2][w][lane];
            float4 s3 = red[3][w][lane];
            float vv[4];
            vv[0] = vals[0] + s1.x + s2.x + s3.x + gin[0];
            vv[1] = vals[1] + s1.y + s2.y + s3.y + gin[1];
            vv[2] = vals[2] + s1.z + s2.z + s3.z + gin[2];
            vv[3] = vals[3] + s1.w + s2.w + s3.w + gin[3];
#pragma unroll
            for (int b = 0; b < 4; b++) gin[b] = ngin[b];

            // gate transpose within lane-groups of 4:
            float x[4];
            x[gate] = vv[b_o];   // k = 0 (self); gate == lane&3 here
#pragma unroll
            for (int k = 1; k < 4; k++) {
                float send = vv[((lane & 3) - k) & 3];
                int src = (lane & ~3) | (((lane & 3) + k) & 3);
                float got = __shfl_sync(0xffffffffu, send, src, 32);
                x[(((lane & 3) + k) & 3)] = got;
            }

            // LSTM update for (u_o, b_o)
            c = sigf(x[1]) * c + sigf(x[0]) * tanh_fast(x[2]);
            float h = sigf(x[3]) * tanh_fast(c);
            hs += h;
            if (t < 511) {
                uint32_t off = (uint32_t)nxt * bstride;
#pragma unroll
                for (int r = 0; r < 8; r++) st_cluster_f32(pbase[r] + off, h);
            }
            // warp-scope release chain: stores -> __syncwarp -> arrive.release;
            // reads-done safety routes through the __syncthreads above.
            __syncwarp();
            if (lane < 8 && t < 511) mbar_arrive_addr(marr);
            houtp[(size_t)t * 16384] = h;
        }
    }
    if (dosum && w < 4)
        hsum[(cl * 4 + b_o) * 256 + k_h] = hs;
}

// ---------------------------------------------------------------------------
// fp32 NT GEMM, 2-stage software-pipelined (double-buffered SMEM):
// C[M=32768][il(N=1024)] = A@B^T + bias, il = (n&255)*4 + (n>>8).
// 64x64 tile, BK=16, 256 threads, 4x4 per thread. grid (16, 512).
// ---------------------------------------------------------------------------
__global__ void __launch_bounds__(256) gemm_nt_kernel(
    const float* __restrict__ A, const float* __restrict__ B,
    const float* __restrict__ bi, const float* __restrict__ bh,
    float* __restrict__ C)
{
    __shared__ float As[2][16][68];
    __shared__ float Bs[2][16][68];
    int tid = threadIdx.x;
    int tx = tid & 15, ty = tid >> 4;
    int bm = blockIdx.y * 64, bn = blockIdx.x * 64;
    int lrow = tid >> 2, lkq = tid & 3;

    unsigned long long accp[4][2];
#pragma unroll
    for (int i = 0; i < 4; i++) { accp[i][0] = 0ull; accp[i][1] = 0ull; }

    const float* Ap = A + (size_t)(bm + lrow) * 256 + lkq * 4;
    const float* Bp = B + (size_t)(bn + lrow) * 256 + lkq * 4;

    float4 av = *(const float4*)(Ap);
    float4 bv = *(const float4*)(Bp);

    int buf = 0;
    for (int kk = 0; kk < 256; kk += 16) {
        As[buf][lkq * 4 + 0][lrow] = av.x; As[buf][lkq * 4 + 1][lrow] = av.y;
        As[buf][lkq * 4 + 2][lrow] = av.z; As[buf][lkq * 4 + 3][lrow] = av.w;
        Bs[buf][lkq * 4 + 0][lrow] = bv.x; Bs[buf][lkq * 4 + 1][lrow] = bv.y;
        Bs[buf][lkq * 4 + 2][lrow] = bv.z; Bs[buf][lkq * 4 + 3][lrow] = bv.w;
        __syncthreads();
        if (kk + 16 < 256) {
            av = *(const float4*)(Ap + kk + 16);
            bv = *(const float4*)(Bp + kk + 16);
        }
#pragma unroll
        for (int k = 0; k < 16; k++) {
            float4 a4 = *(const float4*)&As[buf][k][tx * 4];
            ulonglong2 b2 = *(const ulonglong2*)&Bs[buf][k][ty * 4];
            float am[4] = {a4.x, a4.y, a4.z, a4.w};
#pragma unroll
            for (int i = 0; i < 4; i++) {
                unsigned long long ai = packdup(am[i]);
                ffma2(accp[i][0], ai, b2.x);
                ffma2(accp[i][1], ai, b2.y);
            }
        }
        buf ^= 1;
    }
#pragma unroll
    for (int i = 0; i < 4; i++) {
        size_t rowb = (size_t)(bm + tx * 4 + i) * 1024;
        float2 p0 = *reinterpret_cast<float2*>(&accp[i][0]);
        float2 p1 = *reinterpret_cast<float2*>(&accp[i][1]);
        float vj[4] = {p0.x, p0.y, p1.x, p1.y};
#pragma unroll
        for (int j = 0; j < 4; j++) {
            int n = bn + ty * 4 + j;
            int il = ((n & 255) << 2) | (n >> 8);
            C[rowb + il] = vj[j] + bi[n] + bh[n];
        }
    }
}

// ---------------------------------------------------------------------------
// Phase E: m = hsum/512 ; a[b][n] = m[b].Wl1[n] + b1[n]   (n<100). grid 64.
// ---------------------------------------------------------------------------
__global__ void __launch_bounds__(128) phaseE_kernel(
    const float* __restrict__ hsum, const float* __restrict__ Wl1,
    const float* __restrict__ b1, float* __restrict__ a)
{
    int b = blockIdx.x;
    __shared__ float ms[256];
    for (int i = threadIdx.x; i < 256; i += 128)
        ms[i] = hsum[b * 256 + i] * (1.0f / 512.0f);
    __syncthreads();
    int n = threadIdx.x;
    if (n < 100) {
        const float* wr = Wl1 + (size_t)n * 256;
        float acc = b1[n];
        for (int k = 0; k < 256; k++) acc = fmaf(wr[k], ms[k], acc);
        a[b * 128 + n] = acc;
    }
}

// ---------------------------------------------------------------------------
// Phase F: y[b,t,n] = elu(h1[t,b].Wr1[n] + a[b][n]); chunked sum_t, y at 511.
// ---------------------------------------------------------------------------
__global__ void __launch_bounds__(512) phaseF_kernel(
    const float* __restrict__ h1, const float* __restrict__ Wr1,
    const float* __restrict__ a, float* __restrict__ ypart,
    float* __restrict__ y511)
{
    int chunk = blockIdx.x;
    int b = blockIdx.y;
    int tid = threadIdx.x;
    int n = tid >> 2, kc = tid & 3;
    bool act = (n < 100);

    float w[64];
    if (act) {
        const float4* wp4 = (const float4*)(Wr1 + (size_t)n * 256 + kc * 64);
        float4* w4 = (float4*)w;
#pragma unroll
        for (int i = 0; i < 16; i++) w4[i] = wp4[i];
    }
    float ab = act ? a[b * 128 + n] : 0.0f;

    __shared__ float hsm[256];
    float acc = 0.0f;
    for (int tt = 0; tt < 64; tt++) {
        int t = chunk * 64 + tt;
        if (tid < 64)
            ((float4*)hsm)[tid] = ((const float4*)(h1 + ((size_t)t * 64 + b) * 256))[tid];
        __syncthreads();
        float d = 0.0f;
        if (act) {
            const float4* hp = (const float4*)&hsm[kc * 64];
#pragma unroll
            for (int q = 0; q < 16; q++) {
                float4 h4 = hp[q];
                d = fmaf(w[4 * q + 0], h4.x, d);
                d = fmaf(w[4 * q + 1], h4.y, d);
                d = fmaf(w[4 * q + 2], h4.z, d);
                d = fmaf(w[4 * q + 3], h4.w, d);
            }
        }
        d += __shfl_xor_sync(0xffffffffu, d, 1);
        d += __shfl_xor_sync(0xffffffffu, d, 2);
        if (act && kc == 0) {
            float p = d + ab;
            float y = (p > 0.0f) ? p : expm1f(p);
            acc += y;
            if (t == 511) y511[b * 128 + n] = y;
        }
        __syncthreads();
    }
    if (act && kc == 0) ypart[(chunk * 64 + b) * 128 + n] = acc;
}

// ---------------------------------------------------------------------------
// Phase G: m1 = (sum chunks)/512 ; s[b][d] = m1.Wl2[d] + b2[d] + y511.Wr2[d]
// ---------------------------------------------------------------------------
__global__ void __launch_bounds__(128) phaseG_kernel(
    const float* __restrict__ ypart, const float* __restrict__ y511,
    const float* __restrict__ Wl2, const float* __restrict__ b2,
    const float* __restrict__ Wr2, float* __restrict__ s)
{
    int b = blockIdx.x;
    int tid = threadIdx.x;
    __shared__ float m1[100], yl[100];
    if (tid < 100) {
        float t = 0.0f;
        for (int c2 = 0; c2 < 8; c2++) t += ypart[(c2 * 64 + b) * 128 + tid];
        m1[tid] = t * (1.0f / 512.0f);
        yl[tid] = y511[b * 128 + tid];
    }
    __syncthreads();
    const float* wl = Wl2 + (size_t)tid * 100;
    const float* wr = Wr2 + (size_t)tid * 100;
    float acc = b2[tid];
    for (int n = 0; n < 100; n++) {
        acc = fmaf(m1[n], wl[n], acc);
        acc = fmaf(yl[n], wr[n], acc);
    }
    s[b * 128 + tid] = acc;
}

// ---------------------------------------------------------------------------
// Phase H: z = relu(s.Wfc1 + bfc1); pred = z.Wfc2 + bfc2. grid (8,64), 64 thr.
// ---------------------------------------------------------------------------
__global__ void __launch_bounds__(64) phaseH_kernel(
    const float* __restrict__ s, const float* __restrict__ Wfc1,
    const float* __restrict__ bfc1, const float* __restrict__ Wfc2,
    const float* __restrict__ bfc2, float* __restrict__ out)
{
    int k = blockIdx.x;
    int b = blockIdx.y;
    int o = threadIdx.x;
    __shared__ float ss[128], zz[64];
    ((float2*)ss)[o] = ((const float2*)(s + b * 128))[o];
    __syncthreads();
    {
        const float* w = Wfc1 + ((size_t)k * 64 + o) * 128;
        float acc = bfc1[k * 64 + o];
        for (int d = 0; d < 128; d++) acc = fmaf(w[d], ss[d], acc);
        zz[o] = (acc > 0.0f) ? acc : 0.0f;
    }
    __syncthreads();
    if (o < 24) {
        const float* w2 = Wfc2 + ((size_t)k * 24 + o) * 64;
        float acc = bfc2[k * 24 + o];
        for (int d = 0; d < 64; d++) acc = fmaf(w2[d], zz[d], acc);
        out[((size_t)k * 64 + b) * 24 + o] = acc;
    }
}

// ---------------------------------------------------------------------------
extern "C" void kernel_launch(void* const* d_in, const int* in_sizes, int n_in,
                              void* d_out, int out_size)
{
    const float* x    = (const float*)d_in[0];
    const float* Wih0 = (const float*)d_in[1];
    const float* Whh0 = (const float*)d_in[2];
    const float* bih0 = (const float*)d_in[3];
    const float* bhh0 = (const float*)d_in[4];
    const float* Wih1 = (const float*)d_in[5];
    const float* Whh1 = (const float*)d_in[6];
    const float* bih1 = (const float*)d_in[7];
    const float* bhh1 = (const float*)d_in[8];
    const float* Wl1  = (const float*)d_in[9];
    const float* Wr1  = (const float*)d_in[10];
    const float* b1   = (const float*)d_in[11];
    const float* Wl2  = (const float*)d_in[12];
    const float* Wr2  = (const float*)d_in[13];
    const float* b2   = (const float*)d_in[14];
    const float* Wfc1 = (const float*)d_in[15];
    const float* bfc1 = (const float*)d_in[16];
    const float* Wfc2 = (const float*)d_in[17];
    const float* bfc2 = (const float*)d_in[18];

    float *G, *h0, *h1, *hsum, *a, *ypart, *y511, *s;
    cudaGetSymbolAddress((void**)&G, g_G);
    cudaGetSymbolAddress((void**)&h0, g_h0);
    cudaGetSymbolAddress((void**)&h1, g_h1);
    cudaGetSymbolAddress((void**)&hsum, g_hsum);
    cudaGetSymbolAddress((void**)&a, g_a);
    cudaGetSymbolAddress((void**)&ypart, g_ypart);
    cudaGetSymbolAddress((void**)&y511, g_y511);
    cudaGetSymbolAddress((void**)&s, g_s);

    phaseA_kernel<<<2048, 256>>>(x, Wih0, bih0, bhh0, G);
    lstm_recur_kernel<<<128, 512>>>(G, Whh0, h0, hsum, 0);
    gemm_nt_kernel<<<dim3(16, 512), 256>>>(h0, Wih1, bih1, bhh1, G);
    lstm_recur_kernel<<<128, 512>>>(G, Whh1, h1, hsum, 1);
    phaseE_kernel<<<64, 128>>>(hsum, Wl1, b1, a);
    phaseF_kernel<<<dim3(8, 64), 512>>>(h1, Wr1, a, ypart, y511);
    phaseG_kernel<<<64, 128>>>(ypart, y511, Wl2, b2, Wr2, s);
    phaseH_kernel<<<dim3(8, 64), 64>>>(s, Wfc1, bfc1, Wfc2, bfc2, (float*)d_out);
}

// round 16
// speedup vs baseline: 1.0672x; 1.0672x over previous
#include <cuda_runtime.h>
#include <cuda_bf16.h>
#include <cstdint>
#include <cstddef>

// ---------------------------------------------------------------------------
// Problem: B=64, T=512, K=8, H=256 (4H=1024), HID1=100, HID2=128, OUT=24
// Output: pred (8,64,24) float32
//
// G layout is INTERLEAVED: G[t][b][il] with il = hk*4 + gate for gate row
// r = gate*256 + hk. For recurrence row rl (gate = rl&3, u = rl>>2,
// hk = rank*32+u): il = rank*128 + rl -> coalesced per warp.
// ---------------------------------------------------------------------------

__device__ float g_G[512u * 64u * 1024u];   // interleaved gate pre-activations
__device__ float g_h0[512u * 64u * 256u];   // layer-0 h, time-major [t][b][k]
__device__ float g_h1[512u * 64u * 256u];   // layer-1 h, time-major [t][b][k]
__device__ float g_hsum[64 * 256];          // sum_t h1
__device__ float g_a[64 * 128];             // m@Wl1.T + b1  (100 used)
__device__ float g_ypart[8 * 64 * 128];     // partial sums of y over t-chunks
__device__ float g_y511[64 * 128];          // y at t=511 (100 used)
__device__ float g_s[64 * 128];             // s = h2[:, -1, :]

// ---------------------------------------------------------------------------
// PTX helpers
// ---------------------------------------------------------------------------
__device__ __forceinline__ void cluster_sync_asm() {
    asm volatile("barrier.cluster.arrive.aligned;" ::: "memory");
    asm volatile("barrier.cluster.wait.aligned;" ::: "memory");
}

__device__ __forceinline__ uint32_t mapa_rank(uint32_t laddr, uint32_t rk) {
    uint32_t ra;
    asm volatile("mapa.shared::cluster.u32 %0, %1, %2;" : "=r"(ra) : "r"(laddr), "r"(rk));
    return ra;
}

__device__ __forceinline__ void st_cluster_f32(uint32_t raddr, float v) {
    asm volatile("st.shared::cluster.f32 [%0], %1;" :: "r"(raddr), "f"(v) : "memory");
}

__device__ __forceinline__ void mbar_arrive_addr(uint32_t raddr) {
    asm volatile("mbarrier.arrive.release.cluster.shared::cluster.b64 _, [%0];"
                 :: "r"(raddr) : "memory");
}

__device__ __forceinline__ void mbar_wait_cluster(uint32_t addr, uint32_t parity) {
    asm volatile(
        "{\n\t"
        ".reg .pred P;\n\t"
        "WL%=:\n\t"
        "mbarrier.try_wait.parity.acquire.cluster.shared::cta.b64 P, [%0], %1, 0x989680;\n\t"
        "@P bra.uni WD%=;\n\t"
        "bra.uni WL%=;\n\t"
        "WD%=:\n\t"
        "}" :: "r"(addr), "r"(parity) : "memory");
}

// packed f32x2 fused multiply-add: d = a*b + d
__device__ __forceinline__ void ffma2(unsigned long long& d,
                                      unsigned long long a, unsigned long long b) {
    asm("fma.rn.f32x2 %0, %1, %2, %3;" : "=l"(d) : "l"(a), "l"(b), "l"(d));
}
__device__ __forceinline__ float f2sum(unsigned long long v) {
    float2 f = *reinterpret_cast<float2*>(&v);
    return f.x + f.y;
}
__device__ __forceinline__ unsigned long long packdup(float a) {
    unsigned long long d;
    unsigned int ai = __float_as_uint(a);
    asm("mov.b64 %0, {%1, %1};" : "=l"(d) : "r"(ai));
    return d;
}

__device__ __forceinline__ float sigf(float x) {
    return __fdividef(1.0f, 1.0f + __expf(-x));
}
__device__ __forceinline__ float tanh_fast(float x) {
    return 2.0f * sigf(2.0f * x) - 1.0f;
}

// ---------------------------------------------------------------------------
// Phase A: G0[t][b][il(r)] = (bih0+bhh0)[r] + sum_k x[b][t][k]*Wih0[r][k]
// ---------------------------------------------------------------------------
__global__ void __launch_bounds__(256) phaseA_kernel(
    const float* __restrict__ x, const float* __restrict__ Wih0,
    const float* __restrict__ bih0, const float* __restrict__ bhh0,
    float* __restrict__ G)
{
    __shared__ float xs[16][8];
    int tid = threadIdx.x;
    int p0 = blockIdx.x * 16;

    float w[4][8];
    float bsv[4];
#pragma unroll
    for (int g = 0; g < 4; g++) {
        int r = tid + g * 256;
        const float4* wp = (const float4*)(Wih0 + (size_t)r * 8);
        float4 w0 = wp[0], w1 = wp[1];
        w[g][0] = w0.x; w[g][1] = w0.y; w[g][2] = w0.z; w[g][3] = w0.w;
        w[g][4] = w1.x; w[g][5] = w1.y; w[g][6] = w1.z; w[g][7] = w1.w;
        bsv[g] = bih0[r] + bhh0[r];
    }
    if (tid < 128) {
        int q = tid >> 3, k = tid & 7;
        int p = p0 + q;
        int b = p & 63, t = p >> 6;
        xs[q][k] = x[((size_t)b * 512 + t) * 8 + k];
    }
    __syncthreads();

    for (int q = 0; q < 16; q++) {
        size_t gb = (size_t)(p0 + q) * 1024;
        float4 out;
        float vv[4];
#pragma unroll
        for (int g = 0; g < 4; g++) {
            float acc = bsv[g];
#pragma unroll
            for (int k = 0; k < 8; k++) acc = fmaf(w[g][k], xs[q][k], acc);
            vv[g] = acc;
        }
        out.x = vv[0]; out.y = vv[1]; out.z = vv[2]; out.w = vv[3];
        *(float4*)&G[gb + (size_t)tid * 4] = out;   // il = tid*4 + g
    }
}

// ---------------------------------------------------------------------------
// LSTM recurrence (R13 protocol exactly; only change vs R13: owner warps
// keep their own quarter-0 partials in registers instead of the red[0]
// STS/LDS round-trip). 16 clusters x 8 CTAs (grid 128), 512 threads.
// Broadcast GEMV, quarter mbarriers expect=2, lane0-only polling, prefetch
// above wait, owner tail: push -> bar.sync 1,128 -> tid<8 arrives.
// ---------------------------------------------------------------------------
__global__ void __cluster_dims__(8, 1, 1) __launch_bounds__(512, 1)
lstm_recur_kernel(const float* __restrict__ G, const float* __restrict__ Whh,
                  float* __restrict__ hout, float* __restrict__ hsum, int dosum)
{
    __shared__ float hbuf[2][4][256];          // 8 KB, double-buffered
    __shared__ float4 red[4][4][32];           // [q][rb][lane] -> 8 KB (q=0 unused)
    __shared__ __align__(8) unsigned long long mbar[4];

    int tid = threadIdx.x;
    int rank = blockIdx.x & 7;
    int cl = blockIdx.x >> 3;
    int w = tid >> 5;
    int lane = tid & 31;
    int rb = w & 3;             // row-block
    int q = w >> 2;             // k-quarter (64 cols)
    int rl = rb * 32 + lane;    // row 0..127:  gate = rl&3, u = rl>>2
    int gate = rl & 3;
    int u = rl >> 2;
    int grow = gate * 256 + rank * 32 + u;

    // weights: 64 floats (quarter q of row grow) = 32 packed f32x2
    unsigned long long wreg[32];
    {
        const ulonglong2* wp = (const ulonglong2*)(Whh + (size_t)grow * 256 + q * 64);
#pragma unroll
        for (int i = 0; i < 16; i++) { ulonglong2 v = wp[i]; wreg[2 * i] = v.x; wreg[2 * i + 1] = v.y; }
    }

    for (int i = tid; i < 2 * 4 * 256; i += 512) (&hbuf[0][0][0])[i] = 0.0f;

    uint32_t mbar_addr = (uint32_t)__cvta_generic_to_shared(&mbar[0]);
    if (tid < 4) {
        uint32_t a = mbar_addr + tid * 8;
        asm volatile("mbarrier.init.shared.b64 [%0], 2;" :: "r"(a) : "memory");
    }

    // owner mapping (warps 0-3 only): lane -> (u_o = 8w + lane>>2, b_o = lane&3)
    int b_o = lane & 3;
    int u_o = 8 * w + (lane >> 2);
    int k_h = rank * 32 + u_o;
    uint32_t pbase[8];
    {
        uint32_t lp = (uint32_t)__cvta_generic_to_shared(&hbuf[0][b_o][k_h]);
#pragma unroll
        for (int r = 0; r < 8; r++) pbase[r] = mapa_rank(lp, (uint32_t)r);
    }
    // producer arrive target: barrier index rank>>1 on rank (tid&7)
    uint32_t marr = mapa_rank(mbar_addr + (uint32_t)(rank >> 1) * 8, (uint32_t)(tid & 7));
    // consumer wait address: barrier q (local)
    uint32_t mwait = mbar_addr + (uint32_t)q * 8;
    const uint32_t bstride = 4u * 256u * 4u;   // hbuf[1]-hbuf[0] in bytes

    // interleaved G pointer: il = rank*128 + rl (see header comment)
    const float* gbase = G + (size_t)(cl * 4) * 1024 + rank * 128 + rl;
    float* houtp = hout + (size_t)(cl * 4 + b_o) * 256 + k_h;

    float c = 0.0f, hs = 0.0f;
    __syncthreads();
    cluster_sync_asm();   // mbarriers initialized cluster-wide before any arrive

    float gin[4] = {0, 0, 0, 0};
    if (w < 4) {
#pragma unroll
        for (int b = 0; b < 4; b++) gin[b] = __ldg(gbase + b * 1024);
    }

    for (int t = 0; t < 512; t++) {
        int cur = t & 1;
        int nxt = cur ^ 1;

        // prefetch BEFORE the wait: LDG latency hides under barrier wait
        float ngin[4] = {0, 0, 0, 0};
        if (w < 4) {
            int tn = (t < 511) ? t + 1 : t;
            const float* gp = gbase + (size_t)tn * 65536;
#pragma unroll
            for (int b = 0; b < 4; b++) ngin[b] = __ldg(gp + b * 1024);
        }

        if (t > 0) {
            if (lane == 0) mbar_wait_cluster(mwait, (t + 1) & 1);
            __syncwarp();
        }

        // broadcast GEMV over quarter q
        float vals[4];
#pragma unroll
        for (int b = 0; b < 4; b++) {
            const ulonglong2* hp = (const ulonglong2*)&hbuf[cur][b][q * 64];
            unsigned long long a0 = 0ull, a1 = 0ull;
#pragma unroll
            for (int i = 0; i < 16; i++) {
                ulonglong2 hv = hp[i];
                ffma2(a0, wreg[2 * i], hv.x);
                ffma2(a1, wreg[2 * i + 1], hv.y);
            }
            vals[b] = f2sum(a0) + f2sum(a1);
        }
        if (q != 0)   // owner warps (q==0) keep their partials in registers
            red[q][rb][lane] = make_float4(vals[0], vals[1], vals[2], vals[3]);
        __syncthreads();   // stage-1 partials visible; hbuf[cur] reads done

        if (w < 4) {
            float4 s1 = red[1][w][lane];
            float4 s2 = red[2][w][lane];
            float4 s3 = red[3][w][lane];
            float vv[4];
            vv[0] = vals[0] + s1.x + s2.x + s3.x + gin[0];
            vv[1] = vals[1] + s1.y + s2.y + s3.y + gin[1];
            vv[2] = vals[2] + s1.z + s2.z + s3.z + gin[2];
            vv[3] = vals[3] + s1.w + s2.w + s3.w + gin[3];
#pragma unroll
            for (int b = 0; b < 4; b++) gin[b] = ngin[b];

            // gate transpose within lane-groups of 4:
            float x[4];
            x[gate] = vv[b_o];   // k = 0 (self); gate == lane&3 here
#pragma unroll
            for (int k = 1; k < 4; k++) {
                float send = vv[((lane & 3) - k) & 3];
                int src = (lane & ~3) | (((lane & 3) + k) & 3);
                float got = __shfl_sync(0xffffffffu, send, src, 32);
                x[(((lane & 3) + k) & 3)] = got;
            }

            // LSTM update for (u_o, b_o)
            c = sigf(x[1]) * c + sigf(x[0]) * tanh_fast(x[2]);
            float h = sigf(x[3]) * tanh_fast(c);
            hs += h;
            if (t < 511) {
                uint32_t off = (uint32_t)nxt * bstride;
#pragma unroll
                for (int r = 0; r < 8; r++) st_cluster_f32(pbase[r] + off, h);
            }
            asm volatile("bar.sync 1, 128;" ::: "memory");
            if (tid < 8 && t < 511) mbar_arrive_addr(marr);
            houtp[(size_t)t * 16384] = h;
        }
    }
    if (dosum && w < 4)
        hsum[(cl * 4 + b_o) * 256 + k_h] = hs;
}

// ---------------------------------------------------------------------------
// fp32 NT GEMM, 2-stage software-pipelined (double-buffered SMEM):
// C[M=32768][il(N=1024)] = A@B^T + bias, il = (n&255)*4 + (n>>8).
// 64x64 tile, BK=16, 256 threads, 4x4 per thread. grid (16, 512).
// ---------------------------------------------------------------------------
__global__ void __launch_bounds__(256) gemm_nt_kernel(
    const float* __restrict__ A, const float* __restrict__ B,
    const float* __restrict__ bi, const float* __restrict__ bh,
    float* __restrict__ C)
{
    __shared__ float As[2][16][68];
    __shared__ float Bs[2][16][68];
    int tid = threadIdx.x;
    int tx = tid & 15, ty = tid >> 4;
    int bm = blockIdx.y * 64, bn = blockIdx.x * 64;
    int lrow = tid >> 2, lkq = tid & 3;

    unsigned long long accp[4][2];
#pragma unroll
    for (int i = 0; i < 4; i++) { accp[i][0] = 0ull; accp[i][1] = 0ull; }

    const float* Ap = A + (size_t)(bm + lrow) * 256 + lkq * 4;
    const float* Bp = B + (size_t)(bn + lrow) * 256 + lkq * 4;

    float4 av = *(const float4*)(Ap);
    float4 bv = *(const float4*)(Bp);

    int buf = 0;
    for (int kk = 0; kk < 256; kk += 16) {
        As[buf][lkq * 4 + 0][lrow] = av.x; As[buf][lkq * 4 + 1][lrow] = av.y;
        As[buf][lkq * 4 + 2][lrow] = av.z; As[buf][lkq * 4 + 3][lrow] = av.w;
        Bs[buf][lkq * 4 + 0][lrow] = bv.x; Bs[buf][lkq * 4 + 1][lrow] = bv.y;
        Bs[buf][lkq * 4 + 2][lrow] = bv.z; Bs[buf][lkq * 4 + 3][lrow] = bv.w;
        __syncthreads();
        if (kk + 16 < 256) {
            av = *(const float4*)(Ap + kk + 16);
            bv = *(const float4*)(Bp + kk + 16);
        }
#pragma unroll
        for (int k = 0; k < 16; k++) {
            float4 a4 = *(const float4*)&As[buf][k][tx * 4];
            ulonglong2 b2 = *(const ulonglong2*)&Bs[buf][k][ty * 4];
            float am[4] = {a4.x, a4.y, a4.z, a4.w};
#pragma unroll
            for (int i = 0; i < 4; i++) {
                unsigned long long ai = packdup(am[i]);
                ffma2(accp[i][0], ai, b2.x);
                ffma2(accp[i][1], ai, b2.y);
            }
        }
        buf ^= 1;
    }
#pragma unroll
    for (int i = 0; i < 4; i++) {
        size_t rowb = (size_t)(bm + tx * 4 + i) * 1024;
        float2 p0 = *reinterpret_cast<float2*>(&accp[i][0]);
        float2 p1 = *reinterpret_cast<float2*>(&accp[i][1]);
        float vj[4] = {p0.x, p0.y, p1.x, p1.y};
#pragma unroll
        for (int j = 0; j < 4; j++) {
            int n = bn + ty * 4 + j;
            int il = ((n & 255) << 2) | (n >> 8);
            C[rowb + il] = vj[j] + bi[n] + bh[n];
        }
    }
}

// ---------------------------------------------------------------------------
// Phase E: m = hsum/512 ; a[b][n] = m[b].Wl1[n] + b1[n]   (n<100). grid 64.
// ---------------------------------------------------------------------------
__global__ void __launch_bounds__(128) phaseE_kernel(
    const float* __restrict__ hsum, const float* __restrict__ Wl1,
    const float* __restrict__ b1, float* __restrict__ a)
{
    int b = blockIdx.x;
    __shared__ float ms[256];
    for (int i = threadIdx.x; i < 256; i += 128)
        ms[i] = hsum[b * 256 + i] * (1.0f / 512.0f);
    __syncthreads();
    int n = threadIdx.x;
    if (n < 100) {
        const float* wr = Wl1 + (size_t)n * 256;
        float acc = b1[n];
        for (int k = 0; k < 256; k++) acc = fmaf(wr[k], ms[k], acc);
        a[b * 128 + n] = acc;
    }
}

// ---------------------------------------------------------------------------
// Phase F: y[b,t,n] = elu(h1[t,b].Wr1[n] + a[b][n]); chunked sum_t, y at 511.
// ---------------------------------------------------------------------------
__global__ void __launch_bounds__(512) phaseF_kernel(
    const float* __restrict__ h1, const float* __restrict__ Wr1,
    const float* __restrict__ a, float* __restrict__ ypart,
    float* __restrict__ y511)
{
    int chunk = blockIdx.x;
    int b = blockIdx.y;
    int tid = threadIdx.x;
    int n = tid >> 2, kc = tid & 3;
    bool act = (n < 100);

    float w[64];
    if (act) {
        const float4* wp4 = (const float4*)(Wr1 + (size_t)n * 256 + kc * 64);
        float4* w4 = (float4*)w;
#pragma unroll
        for (int i = 0; i < 16; i++) w4[i] = wp4[i];
    }
    float ab = act ? a[b * 128 + n] : 0.0f;

    __shared__ float hsm[256];
    float acc = 0.0f;
    for (int tt = 0; tt < 64; tt++) {
        int t = chunk * 64 + tt;
        if (tid < 64)
            ((float4*)hsm)[tid] = ((const float4*)(h1 + ((size_t)t * 64 + b) * 256))[tid];
        __syncthreads();
        float d = 0.0f;
        if (act) {
            const float4* hp = (const float4*)&hsm[kc * 64];
#pragma unroll
            for (int q = 0; q < 16; q++) {
                float4 h4 = hp[q];
                d = fmaf(w[4 * q + 0], h4.x, d);
                d = fmaf(w[4 * q + 1], h4.y, d);
                d = fmaf(w[4 * q + 2], h4.z, d);
                d = fmaf(w[4 * q + 3], h4.w, d);
            }
        }
        d += __shfl_xor_sync(0xffffffffu, d, 1);
        d += __shfl_xor_sync(0xffffffffu, d, 2);
        if (act && kc == 0) {
            float p = d + ab;
            float y = (p > 0.0f) ? p : expm1f(p);
            acc += y;
            if (t == 511) y511[b * 128 + n] = y;
        }
        __syncthreads();
    }
    if (act && kc == 0) ypart[(chunk * 64 + b) * 128 + n] = acc;
}

// ---------------------------------------------------------------------------
// Phase G: m1 = (sum chunks)/512 ; s[b][d] = m1.Wl2[d] + b2[d] + y511.Wr2[d]
// ---------------------------------------------------------------------------
__global__ void __launch_bounds__(128) phaseG_kernel(
    const float* __restrict__ ypart, const float* __restrict__ y511,
    const float* __restrict__ Wl2, const float* __restrict__ b2,
    const float* __restrict__ Wr2, float* __restrict__ s)
{
    int b = blockIdx.x;
    int tid = threadIdx.x;
    __shared__ float m1[100], yl[100];
    if (tid < 100) {
        float t = 0.0f;
        for (int c2 = 0; c2 < 8; c2++) t += ypart[(c2 * 64 + b) * 128 + tid];
        m1[tid] = t * (1.0f / 512.0f);
        yl[tid] = y511[b * 128 + tid];
    }
    __syncthreads();
    const float* wl = Wl2 + (size_t)tid * 100;
    const float* wr = Wr2 + (size_t)tid * 100;
    float acc = b2[tid];
    for (int n = 0; n < 100; n++) {
        acc = fmaf(m1[n], wl[n], acc);
        acc = fmaf(yl[n], wr[n], acc);
    }
    s[b * 128 + tid] = acc;
}

// ---------------------------------------------------------------------------
// Phase H: z = relu(s.Wfc1 + bfc1); pred = z.Wfc2 + bfc2. grid (8,64), 64 thr.
// ---------------------------------------------------------------------------
__global__ void __launch_bounds__(64) phaseH_kernel(
    const float* __restrict__ s, const float* __restrict__ Wfc1,
    const float* __restrict__ bfc1, const float* __restrict__ Wfc2,
    const float* __restrict__ bfc2, float* __restrict__ out)
{
    int k = blockIdx.x;
    int b = blockIdx.y;
    int o = threadIdx.x;
    __shared__ float ss[128], zz[64];
    ((float2*)ss)[o] = ((const float2*)(s + b * 128))[o];
    __syncthreads();
    {
        const float* w = Wfc1 + ((size_t)k * 64 + o) * 128;
        float acc = bfc1[k * 64 + o];
        for (int d = 0; d < 128; d++) acc = fmaf(w[d], ss[d], acc);
        zz[o] = (acc > 0.0f) ? acc : 0.0f;
    }
    __syncthreads();
    if (o < 24) {
        const float* w2 = Wfc2 + ((size_t)k * 24 + o) * 64;
        float acc = bfc2[k * 24 + o];
        for (int d = 0; d < 64; d++) acc = fmaf(w2[d], zz[d], acc);
        out[((size_t)k * 64 + b) * 24 + o] = acc;
    }
}

// ---------------------------------------------------------------------------
extern "C" void kernel_launch(void* const* d_in, const int* in_sizes, int n_in,
                              void* d_out, int out_size)
{
    const float* x    = (const float*)d_in[0];
    const float* Wih0 = (const float*)d_in[1];
    const float* Whh0 = (const float*)d_in[2];
    const float* bih0 = (const float*)d_in[3];
    const float* bhh0 = (const float*)d_in[4];
    const float* Wih1 = (const float*)d_in[5];
    const float* Whh1 = (const float*)d_in[6];
    const float* bih1 = (const float*)d_in[7];
    const float* bhh1 = (const float*)d_in[8];
    const float* Wl1  = (const float*)d_in[9];
    const float* Wr1  = (const float*)d_in[10];
    const float* b1   = (const float*)d_in[11];
    const float* Wl2  = (const float*)d_in[12];
    const float* Wr2  = (const float*)d_in[13];
    const float* b2   = (const float*)d_in[14];
    const float* Wfc1 = (const float*)d_in[15];
    const float* bfc1 = (const float*)d_in[16];
    const float* Wfc2 = (const float*)d_in[17];
    const float* bfc2 = (const float*)d_in[18];

    float *G, *h0, *h1, *hsum, *a, *ypart, *y511, *s;
    cudaGetSymbolAddress((void**)&G, g_G);
    cudaGetSymbolAddress((void**)&h0, g_h0);
    cudaGetSymbolAddress((void**)&h1, g_h1);
    cudaGetSymbolAddress((void**)&hsum, g_hsum);
    cudaGetSymbolAddress((void**)&a, g_a);
    cudaGetSymbolAddress((void**)&ypart, g_ypart);
    cudaGetSymbolAddress((void**)&y511, g_y511);
    cudaGetSymbolAddress((void**)&s, g_s);

    phaseA_kernel<<<2048, 256>>>(x, Wih0, bih0, bhh0, G);
    lstm_recur_kernel<<<128, 512>>>(G, Whh0, h0, hsum, 0);
    gemm_nt_kernel<<<dim3(16, 512), 256>>>(h0, Wih1, bih1, bhh1, G);
    lstm_recur_kernel<<<128, 512>>>(G, Whh1, h1, hsum, 1);
    phaseE_kernel<<<64, 128>>>(hsum, Wl1, b1, a);
    phaseF_kernel<<<dim3(8, 64), 512>>>(h1, Wr1, a, ypart, y511);
    phaseG_kernel<<<64, 128>>>(ypart, y511, Wl2, b2, Wr2, s);
    phaseH_kernel<<<dim3(8, 64), 64>>>(s, Wfc1, bfc1, Wfc2, bfc2, (float*)d_out);
}

// round 17
// speedup vs baseline: 1.1377x; 1.0661x over previous
#include <cuda_runtime.h>
#include <cuda_bf16.h>
#include <cstdint>
#include <cstddef>

// ---------------------------------------------------------------------------
// Problem: B=64, T=512, K=8, H=256 (4H=1024), HID1=100, HID2=128, OUT=24
// Output: pred (8,64,24) float32
//
// G layout is INTERLEAVED: G[t][b][il] with il = hk*4 + gate for gate row
// r = gate*256 + hk. For recurrence row rl (gate = rl&3, u = rl>>2,
// hk = rank*32+u): il = rank*128 + rl -> coalesced per warp.
// ---------------------------------------------------------------------------

__device__ float g_G[512u * 64u * 1024u];   // interleaved gate pre-activations
__device__ float g_h0[512u * 64u * 256u];   // layer-0 h, time-major [t][b][k]
__device__ float g_h1[512u * 64u * 256u];   // layer-1 h, time-major [t][b][k]
__device__ float g_hsum[64 * 256];          // sum_t h1
__device__ float g_a[64 * 128];             // m@Wl1.T + b1  (100 used)
__device__ float g_ypart[8 * 64 * 128];     // partial sums of y over t-chunks
__device__ float g_y511[64 * 128];          // y at t=511 (100 used)
__device__ float g_s[64 * 128];             // s = h2[:, -1, :]

// ---------------------------------------------------------------------------
// PTX helpers
// ---------------------------------------------------------------------------
__device__ __forceinline__ void cluster_sync_asm() {
    asm volatile("barrier.cluster.arrive.aligned;" ::: "memory");
    asm volatile("barrier.cluster.wait.aligned;" ::: "memory");
}

__device__ __forceinline__ uint32_t mapa_rank(uint32_t laddr, uint32_t rk) {
    uint32_t ra;
    asm volatile("mapa.shared::cluster.u32 %0, %1, %2;" : "=r"(ra) : "r"(laddr), "r"(rk));
    return ra;
}

__device__ __forceinline__ void st_cluster_f32(uint32_t raddr, float v) {
    asm volatile("st.shared::cluster.f32 [%0], %1;" :: "r"(raddr), "f"(v) : "memory");
}

__device__ __forceinline__ void mbar_arrive_addr(uint32_t raddr) {
    asm volatile("mbarrier.arrive.release.cluster.shared::cluster.b64 _, [%0];"
                 :: "r"(raddr) : "memory");
}

__device__ __forceinline__ void mbar_wait_cluster(uint32_t addr, uint32_t parity) {
    asm volatile(
        "{\n\t"
        ".reg .pred P;\n\t"
        "WL%=:\n\t"
        "mbarrier.try_wait.parity.acquire.cluster.shared::cta.b64 P, [%0], %1, 0x989680;\n\t"
        "@P bra.uni WD%=;\n\t"
        "bra.uni WL%=;\n\t"
        "WD%=:\n\t"
        "}" :: "r"(addr), "r"(parity) : "memory");
}

// packed f32x2 fused multiply-add: d = a*b + d
__device__ __forceinline__ void ffma2(unsigned long long& d,
                                      unsigned long long a, unsigned long long b) {
    asm("fma.rn.f32x2 %0, %1, %2, %3;" : "=l"(d) : "l"(a), "l"(b), "l"(d));
}
__device__ __forceinline__ float f2sum(unsigned long long v) {
    float2 f = *reinterpret_cast<float2*>(&v);
    return f.x + f.y;
}
__device__ __forceinline__ unsigned long long packdup(float a) {
    unsigned long long d;
    unsigned int ai = __float_as_uint(a);
    asm("mov.b64 %0, {%1, %1};" : "=l"(d) : "r"(ai));
    return d;
}

__device__ __forceinline__ float sigf(float x) {
    return __fdividef(1.0f, 1.0f + __expf(-x));
}
__device__ __forceinline__ float tanh_fast(float x) {
    return 2.0f * sigf(2.0f * x) - 1.0f;
}

// ---------------------------------------------------------------------------
// Phase A: G0[t][b][il(r)] = (bih0+bhh0)[r] + sum_k x[b][t][k]*Wih0[r][k]
// ---------------------------------------------------------------------------
__global__ void __launch_bounds__(256) phaseA_kernel(
    const float* __restrict__ x, const float* __restrict__ Wih0,
    const float* __restrict__ bih0, const float* __restrict__ bhh0,
    float* __restrict__ G)
{
    __shared__ float xs[16][8];
    int tid = threadIdx.x;
    int p0 = blockIdx.x * 16;

    float w[4][8];
    float bsv[4];
#pragma unroll
    for (int g = 0; g < 4; g++) {
        int r = tid + g * 256;
        const float4* wp = (const float4*)(Wih0 + (size_t)r * 8);
        float4 w0 = wp[0], w1 = wp[1];
        w[g][0] = w0.x; w[g][1] = w0.y; w[g][2] = w0.z; w[g][3] = w0.w;
        w[g][4] = w1.x; w[g][5] = w1.y; w[g][6] = w1.z; w[g][7] = w1.w;
        bsv[g] = bih0[r] + bhh0[r];
    }
    if (tid < 128) {
        int q = tid >> 3, k = tid & 7;
        int p = p0 + q;
        int b = p & 63, t = p >> 6;
        xs[q][k] = x[((size_t)b * 512 + t) * 8 + k];
    }
    __syncthreads();

    for (int q = 0; q < 16; q++) {
        size_t gb = (size_t)(p0 + q) * 1024;
        float4 out;
        float vv[4];
#pragma unroll
        for (int g = 0; g < 4; g++) {
            float acc = bsv[g];
#pragma unroll
            for (int k = 0; k < 8; k++) acc = fmaf(w[g][k], xs[q][k], acc);
            vv[g] = acc;
        }
        out.x = vv[0]; out.y = vv[1]; out.z = vv[2]; out.w = vv[3];
        *(float4*)&G[gb + (size_t)tid * 4] = out;   // il = tid*4 + g
    }
}

// ---------------------------------------------------------------------------
// LSTM recurrence (R16 exactly — best measured). 16 clusters x 8 CTAs
// (grid 128), 512 threads. Broadcast GEMV, quarter mbarriers expect=2,
// lane0-only polling, prefetch above wait, owner q==0 partials in registers.
// ---------------------------------------------------------------------------
__global__ void __cluster_dims__(8, 1, 1) __launch_bounds__(512, 1)
lstm_recur_kernel(const float* __restrict__ G, const float* __restrict__ Whh,
                  float* __restrict__ hout, float* __restrict__ hsum, int dosum)
{
    __shared__ float hbuf[2][4][256];          // 8 KB, double-buffered
    __shared__ float4 red[4][4][32];           // [q][rb][lane] (q=0 unused)
    __shared__ __align__(8) unsigned long long mbar[4];

    int tid = threadIdx.x;
    int rank = blockIdx.x & 7;
    int cl = blockIdx.x >> 3;
    int w = tid >> 5;
    int lane = tid & 31;
    int rb = w & 3;             // row-block
    int q = w >> 2;             // k-quarter (64 cols)
    int rl = rb * 32 + lane;    // row 0..127:  gate = rl&3, u = rl>>2
    int gate = rl & 3;
    int u = rl >> 2;
    int grow = gate * 256 + rank * 32 + u;

    // weights: 64 floats (quarter q of row grow) = 32 packed f32x2
    unsigned long long wreg[32];
    {
        const ulonglong2* wp = (const ulonglong2*)(Whh + (size_t)grow * 256 + q * 64);
#pragma unroll
        for (int i = 0; i < 16; i++) { ulonglong2 v = wp[i]; wreg[2 * i] = v.x; wreg[2 * i + 1] = v.y; }
    }

    for (int i = tid; i < 2 * 4 * 256; i += 512) (&hbuf[0][0][0])[i] = 0.0f;

    uint32_t mbar_addr = (uint32_t)__cvta_generic_to_shared(&mbar[0]);
    if (tid < 4) {
        uint32_t a = mbar_addr + tid * 8;
        asm volatile("mbarrier.init.shared.b64 [%0], 2;" :: "r"(a) : "memory");
    }

    // owner mapping (warps 0-3 only): lane -> (u_o = 8w + lane>>2, b_o = lane&3)
    int b_o = lane & 3;
    int u_o = 8 * w + (lane >> 2);
    int k_h = rank * 32 + u_o;
    uint32_t pbase[8];
    {
        uint32_t lp = (uint32_t)__cvta_generic_to_shared(&hbuf[0][b_o][k_h]);
#pragma unroll
        for (int r = 0; r < 8; r++) pbase[r] = mapa_rank(lp, (uint32_t)r);
    }
    // producer arrive target: barrier index rank>>1 on rank (tid&7)
    uint32_t marr = mapa_rank(mbar_addr + (uint32_t)(rank >> 1) * 8, (uint32_t)(tid & 7));
    // consumer wait address: barrier q (local)
    uint32_t mwait = mbar_addr + (uint32_t)q * 8;
    const uint32_t bstride = 4u * 256u * 4u;   // hbuf[1]-hbuf[0] in bytes

    // interleaved G pointer: il = rank*128 + rl (see header comment)
    const float* gbase = G + (size_t)(cl * 4) * 1024 + rank * 128 + rl;
    float* houtp = hout + (size_t)(cl * 4 + b_o) * 256 + k_h;

    float c = 0.0f, hs = 0.0f;
    __syncthreads();
    cluster_sync_asm();   // mbarriers initialized cluster-wide before any arrive

    float gin[4] = {0, 0, 0, 0};
    if (w < 4) {
#pragma unroll
        for (int b = 0; b < 4; b++) gin[b] = __ldg(gbase + b * 1024);
    }

    for (int t = 0; t < 512; t++) {
        int cur = t & 1;
        int nxt = cur ^ 1;

        // prefetch BEFORE the wait: LDG latency hides under barrier wait
        float ngin[4] = {0, 0, 0, 0};
        if (w < 4) {
            int tn = (t < 511) ? t + 1 : t;
            const float* gp = gbase + (size_t)tn * 65536;
#pragma unroll
            for (int b = 0; b < 4; b++) ngin[b] = __ldg(gp + b * 1024);
        }

        if (t > 0) {
            if (lane == 0) mbar_wait_cluster(mwait, (t + 1) & 1);
            __syncwarp();
        }

        // broadcast GEMV over quarter q
        float vals[4];
#pragma unroll
        for (int b = 0; b < 4; b++) {
            const ulonglong2* hp = (const ulonglong2*)&hbuf[cur][b][q * 64];
            unsigned long long a0 = 0ull, a1 = 0ull;
#pragma unroll
            for (int i = 0; i < 16; i++) {
                ulonglong2 hv = hp[i];
                ffma2(a0, wreg[2 * i], hv.x);
                ffma2(a1, wreg[2 * i + 1], hv.y);
            }
            vals[b] = f2sum(a0) + f2sum(a1);
        }
        if (q != 0)   // owner warps (q==0) keep their partials in registers
            red[q][rb][lane] = make_float4(vals[0], vals[1], vals[2], vals[3]);
        __syncthreads();   // stage-1 partials visible; hbuf[cur] reads done

        if (w < 4) {
            float4 s1 = red[1][w][lane];
            float4 s2 = red[2][w][lane];
            float4 s3 = red[3][w][lane];
            float vv[4];
            vv[0] = vals[0] + s1.x + s2.x + s3.x + gin[0];
            vv[1] = vals[1] + s1.y + s2.y + s3.y + gin[1];
            vv[2] = vals[2] + s1.z + s2.z + s3.z + gin[2];
            vv[3] = vals[3] + s1.w + s2.w + s3.w + gin[3];
#pragma unroll
            for (int b = 0; b < 4; b++) gin[b] = ngin[b];

            // gate transpose within lane-groups of 4:
            float x[4];
            x[gate] = vv[b_o];   // k = 0 (self); gate == lane&3 here
#pragma unroll
            for (int k = 1; k < 4; k++) {
                float send = vv[((lane & 3) - k) & 3];
                int src = (lane & ~3) | (((lane & 3) + k) & 3);
                float got = __shfl_sync(0xffffffffu, send, src, 32);
                x[(((lane & 3) + k) & 3)] = got;
            }

            // LSTM update for (u_o, b_o)
            c = sigf(x[1]) * c + sigf(x[0]) * tanh_fast(x[2]);
            float h = sigf(x[3]) * tanh_fast(c);
            hs += h;
            if (t < 511) {
                uint32_t off = (uint32_t)nxt * bstride;
#pragma unroll
                for (int r = 0; r < 8; r++) st_cluster_f32(pbase[r] + off, h);
            }
            asm volatile("bar.sync 1, 128;" ::: "memory");
            if (tid < 8 && t < 511) mbar_arrive_addr(marr);
            houtp[(size_t)t * 16384] = h;
        }
    }
    if (dosum && w < 4)
        hsum[(cl * 4 + b_o) * 256 + k_h] = hs;
}

// ---------------------------------------------------------------------------
// fp32 NT GEMM, 128x64 tile, BK=16, 256 threads, 8x4 per thread, 2-stage
// double-buffered. C[M=32768][il(N=1024)] = A@B^T + bias,
// il = (n&255)*4 + (n>>8). grid (16, 256). Per-output k-order identical to
// previous version (bit-identical results).
// ---------------------------------------------------------------------------
__global__ void __launch_bounds__(256) gemm_nt_kernel(
    const float* __restrict__ A, const float* __restrict__ B,
    const float* __restrict__ bi, const float* __restrict__ bh,
    float* __restrict__ C)
{
    __shared__ float As[2][16][136];
    __shared__ float Bs[2][16][72];
    int tid = threadIdx.x;
    int tx = tid & 15, ty = tid >> 4;
    int bm = blockIdx.y * 128, bn = blockIdx.x * 64;
    int lr = tid >> 2, lc = (tid & 3) * 4;

    unsigned long long accp[8][2];
#pragma unroll
    for (int i = 0; i < 8; i++) { accp[i][0] = 0ull; accp[i][1] = 0ull; }

    const float* Ap0 = A + (size_t)(bm + lr) * 256 + lc;
    const float* Ap1 = A + (size_t)(bm + lr + 64) * 256 + lc;
    const float* Bp  = B + (size_t)(bn + lr) * 256 + lc;

    float4 av0 = *(const float4*)Ap0;
    float4 av1 = *(const float4*)Ap1;
    float4 bv  = *(const float4*)Bp;

    int buf = 0;
    for (int kk = 0; kk < 256; kk += 16) {
        As[buf][lc + 0][lr] = av0.x; As[buf][lc + 1][lr] = av0.y;
        As[buf][lc + 2][lr] = av0.z; As[buf][lc + 3][lr] = av0.w;
        As[buf][lc + 0][lr + 64] = av1.x; As[buf][lc + 1][lr + 64] = av1.y;
        As[buf][lc + 2][lr + 64] = av1.z; As[buf][lc + 3][lr + 64] = av1.w;
        Bs[buf][lc + 0][lr] = bv.x; Bs[buf][lc + 1][lr] = bv.y;
        Bs[buf][lc + 2][lr] = bv.z; Bs[buf][lc + 3][lr] = bv.w;
        __syncthreads();
        if (kk + 16 < 256) {
            av0 = *(const float4*)(Ap0 + kk + 16);
            av1 = *(const float4*)(Ap1 + kk + 16);
            bv  = *(const float4*)(Bp + kk + 16);
        }
#pragma unroll
        for (int k = 0; k < 16; k++) {
            float4 a0 = *(const float4*)&As[buf][k][ty * 8];
            float4 a1 = *(const float4*)&As[buf][k][ty * 8 + 4];
            ulonglong2 b2 = *(const ulonglong2*)&Bs[buf][k][tx * 4];
            float am[8] = {a0.x, a0.y, a0.z, a0.w, a1.x, a1.y, a1.z, a1.w};
#pragma unroll
            for (int i = 0; i < 8; i++) {
                unsigned long long ai = packdup(am[i]);
                ffma2(accp[i][0], ai, b2.x);
                ffma2(accp[i][1], ai, b2.y);
            }
        }
        buf ^= 1;
    }
#pragma unroll
    for (int i = 0; i < 8; i++) {
        size_t rowb = (size_t)(bm + ty * 8 + i) * 1024;
        float2 p0 = *reinterpret_cast<float2*>(&accp[i][0]);
        float2 p1 = *reinterpret_cast<float2*>(&accp[i][1]);
        float vj[4] = {p0.x, p0.y, p1.x, p1.y};
#pragma unroll
        for (int j = 0; j < 4; j++) {
            int n = bn + tx * 4 + j;
            int il = ((n & 255) << 2) | (n >> 8);
            C[rowb + il] = vj[j] + bi[n] + bh[n];
        }
    }
}

// ---------------------------------------------------------------------------
// Phase E: m = hsum/512 ; a[b][n] = m[b].Wl1[n] + b1[n]   (n<100). grid 64.
// ---------------------------------------------------------------------------
__global__ void __launch_bounds__(128) phaseE_kernel(
    const float* __restrict__ hsum, const float* __restrict__ Wl1,
    const float* __restrict__ b1, float* __restrict__ a)
{
    int b = blockIdx.x;
    __shared__ float ms[256];
    for (int i = threadIdx.x; i < 256; i += 128)
        ms[i] = hsum[b * 256 + i] * (1.0f / 512.0f);
    __syncthreads();
    int n = threadIdx.x;
    if (n < 100) {
        const float* wr = Wl1 + (size_t)n * 256;
        float acc = b1[n];
        for (int k = 0; k < 256; k++) acc = fmaf(wr[k], ms[k], acc);
        a[b * 128 + n] = acc;
    }
}

// ---------------------------------------------------------------------------
// Phase F: y[b,t,n] = elu(h1[t,b].Wr1[n] + a[b][n]); chunked sum_t, y at 511.
// hsm padded to 272 floats (chunk kc at offset kc*68) -> conflict-free LDS.
// ---------------------------------------------------------------------------
__global__ void __launch_bounds__(512) phaseF_kernel(
    const float* __restrict__ h1, const float* __restrict__ Wr1,
    const float* __restrict__ a, float* __restrict__ ypart,
    float* __restrict__ y511)
{
    int chunk = blockIdx.x;
    int b = blockIdx.y;
    int tid = threadIdx.x;
    int n = tid >> 2, kc = tid & 3;
    bool act = (n < 100);

    float w[64];
    if (act) {
        const float4* wp4 = (const float4*)(Wr1 + (size_t)n * 256 + kc * 64);
        float4* w4 = (float4*)w;
#pragma unroll
        for (int i = 0; i < 16; i++) w4[i] = wp4[i];
    }
    float ab = act ? a[b * 128 + n] : 0.0f;

    __shared__ float hsm[272];
    float acc = 0.0f;
    for (int tt = 0; tt < 64; tt++) {
        int t = chunk * 64 + tt;
        if (tid < 64) {
            float4 v = ((const float4*)(h1 + ((size_t)t * 64 + b) * 256))[tid];
            *(float4*)&hsm[tid * 4 + ((tid >> 4) << 2)] = v;
        }
        __syncthreads();
        float d = 0.0f;
        if (act) {
            const float4* hp = (const float4*)&hsm[kc * 68];
#pragma unroll
            for (int q = 0; q < 16; q++) {
                float4 h4 = hp[q];
                d = fmaf(w[4 * q + 0], h4.x, d);
                d = fmaf(w[4 * q + 1], h4.y, d);
                d = fmaf(w[4 * q + 2], h4.z, d);
                d = fmaf(w[4 * q + 3], h4.w, d);
            }
        }
        d += __shfl_xor_sync(0xffffffffu, d, 1);
        d += __shfl_xor_sync(0xffffffffu, d, 2);
        if (act && kc == 0) {
            float p = d + ab;
            float y = (p > 0.0f) ? p : expm1f(p);
            acc += y;
            if (t == 511) y511[b * 128 + n] = y;
        }
        __syncthreads();
    }
    if (act && kc == 0) ypart[(chunk * 64 + b) * 128 + n] = acc;
}

// ---------------------------------------------------------------------------
// Phase G: m1 = (sum chunks)/512 ; s[b][d] = m1.Wl2[d] + b2[d] + y511.Wr2[d]
// ---------------------------------------------------------------------------
__global__ void __launch_bounds__(128) phaseG_kernel(
    const float* __restrict__ ypart, const float* __restrict__ y511,
    const float* __restrict__ Wl2, const float* __restrict__ b2,
    const float* __restrict__ Wr2, float* __restrict__ s)
{
    int b = blockIdx.x;
    int tid = threadIdx.x;
    __shared__ float m1[100], yl[100];
    if (tid < 100) {
        float t = 0.0f;
        for (int c2 = 0; c2 < 8; c2++) t += ypart[(c2 * 64 + b) * 128 + tid];
        m1[tid] = t * (1.0f / 512.0f);
        yl[tid] = y511[b * 128 + tid];
    }
    __syncthreads();
    const float* wl = Wl2 + (size_t)tid * 100;
    const float* wr = Wr2 + (size_t)tid * 100;
    float acc = b2[tid];
    for (int n = 0; n < 100; n++) {
        acc = fmaf(m1[n], wl[n], acc);
        acc = fmaf(yl[n], wr[n], acc);
    }
    s[b * 128 + tid] = acc;
}

// ---------------------------------------------------------------------------
// Phase H: z = relu(s.Wfc1 + bfc1); pred = z.Wfc2 + bfc2. grid (8,64), 64 thr.
// ---------------------------------------------------------------------------
__global__ void __launch_bounds__(64) phaseH_kernel(
    const float* __restrict__ s, const float* __restrict__ Wfc1,
    const float* __restrict__ bfc1, const float* __restrict__ Wfc2,
    const float* __restrict__ bfc2, float* __restrict__ out)
{
    int k = blockIdx.x;
    int b = blockIdx.y;
    int o = threadIdx.x;
    __shared__ float ss[128], zz[64];
    ((float2*)ss)[o] = ((const float2*)(s + b * 128))[o];
    __syncthreads();
    {
        const float* w = Wfc1 + ((size_t)k * 64 + o) * 128;
        float acc = bfc1[k * 64 + o];
        for (int d = 0; d < 128; d++) acc = fmaf(w[d], ss[d], acc);
        zz[o] = (acc > 0.0f) ? acc : 0.0f;
    }
    __syncthreads();
    if (o < 24) {
        const float* w2 = Wfc2 + ((size_t)k * 24 + o) * 64;
        float acc = bfc2[k * 24 + o];
        for (int d = 0; d < 64; d++) acc = fmaf(w2[d], zz[d], acc);
        out[((size_t)k * 64 + b) * 24 + o] = acc;
    }
}

// ---------------------------------------------------------------------------
extern "C" void kernel_launch(void* const* d_in, const int* in_sizes, int n_in,
                              void* d_out, int out_size)
{
    const float* x    = (const float*)d_in[0];
    const float* Wih0 = (const float*)d_in[1];
    const float* Whh0 = (const float*)d_in[2];
    const float* bih0 = (const float*)d_in[3];
    const float* bhh0 = (const float*)d_in[4];
    const float* Wih1 = (const float*)d_in[5];
    const float* Whh1 = (const float*)d_in[6];
    const float* bih1 = (const float*)d_in[7];
    const float* bhh1 = (const float*)d_in[8];
    const float* Wl1  = (const float*)d_in[9];
    const float* Wr1  = (const float*)d_in[10];
    const float* b1   = (const float*)d_in[11];
    const float* Wl2  = (const float*)d_in[12];
    const float* Wr2  = (const float*)d_in[13];
    const float* b2   = (const float*)d_in[14];
    const float* Wfc1 = (const float*)d_in[15];
    const float* bfc1 = (const float*)d_in[16];
    const float* Wfc2 = (const float*)d_in[17];
    const float* bfc2 = (const float*)d_in[18];

    float *G, *h0, *h1, *hsum, *a, *ypart, *y511, *s;
    cudaGetSymbolAddress((void**)&G, g_G);
    cudaGetSymbolAddress((void**)&h0, g_h0);
    cudaGetSymbolAddress((void**)&h1, g_h1);
    cudaGetSymbolAddress((void**)&hsum, g_hsum);
    cudaGetSymbolAddress((void**)&a, g_a);
    cudaGetSymbolAddress((void**)&ypart, g_ypart);
    cudaGetSymbolAddress((void**)&y511, g_y511);
    cudaGetSymbolAddress((void**)&s, g_s);

    phaseA_kernel<<<2048, 256>>>(x, Wih0, bih0, bhh0, G);
    lstm_recur_kernel<<<128, 512>>>(G, Whh0, h0, hsum, 0);
    gemm_nt_kernel<<<dim3(16, 256), 256>>>(h0, Wih1, bih1, bhh1, G);
    lstm_recur_kernel<<<128, 512>>>(G, Whh1, h1, hsum, 1);
    phaseE_kernel<<<64, 128>>>(hsum, Wl1, b1, a);
    phaseF_kernel<<<dim3(8, 64), 512>>>(h1, Wr1, a, ypart, y511);
    phaseG_kernel<<<64, 128>>>(ypart, y511, Wl2, b2, Wr2, s);
    phaseH_kernel<<<dim3(8, 64), 64>>>(s, Wfc1, bfc1, Wfc2, bfc2, (float*)d_out);
}